// round 17
// baseline (speedup 1.0000x reference)
#include <cuda_runtime.h>

// ---------------------------------------------------------------------------
// EquivGNNEncoder on GB300, v13 = v8 + fold-packed Wd16 weights (W2/W3/Wv).
// R15 forensics: reduction-pair packing QUADRUPLED Wd32 weight wavefronts
// (32B-stride lanes) but HALVED Wd16 ones (contiguous 128B). v13 applies it
// only where it wins: W2/W3/Wv packed (W[2u][w],W[2u+1][w]) with C_VI/0.25
// folded; inputs read as contiguous u64 pairs (no splats); (even,odd)
// partials folded by one FADD per output. Everything else = v8 (201.8us).
// ---------------------------------------------------------------------------

#define MAXN (1 << 17)
#define MAXB 4096
#define WPAKN (3 * 1024)

typedef unsigned long long u64;

__device__ float g_hg[MAXB * 80];
__device__ float g_wp[WPAKN];   // per layer 1024: [W2' 512 | W3' 256 | Wv' 256]

__device__ __forceinline__ void cpa16(void* s, const void* g) {
    unsigned sa = (unsigned)__cvta_generic_to_shared(s);
    asm volatile("cp.async.cg.shared.global [%0], [%1], 16;\n" :: "r"(sa), "l"(g));
}
__device__ __forceinline__ void cpa_commit() {
    asm volatile("cp.async.commit_group;\n");
}
template<int N> __device__ __forceinline__ void cpa_wait() {
    asm volatile("cp.async.wait_group %0;\n" :: "n"(N) : "memory");
}

__device__ __forceinline__ u64 pk2(float lo, float hi) {
    u64 r; asm("mov.b64 %0, {%1, %2};" : "=l"(r) : "f"(lo), "f"(hi)); return r;
}
__device__ __forceinline__ u64 splat2(float v) { return pk2(v, v); }
__device__ __forceinline__ void upk2(u64 v, float& lo, float& hi) {
    asm("mov.b64 {%0, %1}, %2;" : "=f"(lo), "=f"(hi) : "l"(v));
}
__device__ __forceinline__ float fold2(u64 v) {
    float lo, hi; upk2(v, lo, hi); return lo + hi;
}
__device__ __forceinline__ void ffma2(u64& d, u64 a, u64 b) {
    asm("fma.rn.f32x2 %0, %1, %2, %0;" : "+l"(d) : "l"(a), "l"(b));
}
__device__ __forceinline__ void fadd2(u64& d, u64 a) {
    asm("add.rn.f32x2 %0, %1, %0;" : "+l"(d) : "l"(a));
}

// pack Wd16 matrices, reduction-pair interleaved with scales folded:
// dst (per matrix) = (u>>1)*32 + w*2 + (u&1)   [U16 matrices: same formula]
__global__ void k_pack(const float* __restrict__ W2, const float* __restrict__ W3,
                       const float* __restrict__ Wv)
{
    const float C_VI = 0.14433756729740643f;
    int i = blockIdx.x * blockDim.x + threadIdx.x;
    if (i >= WPAKN) return;
    int l = i >> 10, k2 = i & 1023;
    float v;
    if (k2 < 512) {                       // W2: 32x16
        int j = k2 >> 5, r = k2 & 31, w = r >> 1, h = r & 1;
        v = W2[l * 512 + (2 * j + h) * 16 + w] * C_VI;
    } else if (k2 < 768) {                // W3: 16x16
        int q = k2 - 512;
        int j = q >> 5, r = q & 31, w = r >> 1, h = r & 1;
        v = W3[l * 256 + (2 * j + h) * 16 + w] * C_VI;
    } else {                              // Wv: 16x16, fold 0.25
        int q = k2 - 768;
        int j = q >> 5, r = q & 31, w = r >> 1, h = r & 1;
        v = Wv[l * 256 + (2 * j + h) * 16 + w] * 0.25f;
    }
    g_wp[i] = v;
}

// smem float offsets (total 14272 floats = 57088 B -> 4 CTAs/SM):
#define SPOS 0        // pos float4 [32]        (128)
#define SS   128      // [n] stride 36          (1152)
#define SV4  1280     // float4 [n*17+w]        (2176)
#define SSB  3456     // S_bar [n] stride 36    (1152)
#define SR   4608     // r [n] stride 20        (640)
#define SVB  5248     // Vbar [(n*3+i)]*20      (1920)
#define SP   7168     // p [(n*3+i)]*36         (3456)
#define SAS  7168     // alias over sP          (1152)
#define SAV  8320     // alias over sP          (1920)
#define SW   10624    // 3584: [W1 0|W2' 1024|W3' 1536|W4 1792|Ws 2304|Wv' 3328]
#define SADJ 14208
#define SZI  14240
#define SMEM_GNN (14272 * 4)

// packed Wd16 matvecs: b0/b1 accumulate (even-u, odd-u) partials for the two
// output cols (2q8, 2q8+1); fold at the end.
__device__ __forceinline__ void mv32x16p(const u64* ip, const ulonglong2* wp,
                                         int q8, u64& b0, u64& b1)
{
    #pragma unroll
    for (int k = 0; k < 16; ++k) {
        u64 in2 = ip[k];
        ulonglong2 w = wp[k * 8 + q8];
        ffma2(b0, in2, w.x);
        ffma2(b1, in2, w.y);
    }
}
__device__ __forceinline__ void mv16x16p(const u64* ip, const ulonglong2* wp,
                                         int q8, u64& b0, u64& b1)
{
    #pragma unroll
    for (int k = 0; k < 8; ++k) {
        u64 in2 = ip[k];
        ulonglong2 w = wp[k * 8 + q8];
        ffma2(b0, in2, w.x);
        ffma2(b1, in2, w.y);
    }
}

__global__ void __launch_bounds__(256, 4) k_gnn(
    const float* __restrict__ pos, const int* __restrict__ z,
    const float* __restrict__ emb, const float* __restrict__ Ws2n,
    const float* __restrict__ W1g, const float* __restrict__ W4g,
    const float* __restrict__ Wsg)
{
    extern __shared__ float sm[];
    float* sW = sm + SW;
    unsigned* sAdj = (unsigned*)(sm + SADJ);
    int*      sZi  = (int*)(sm + SZI);

    const int g    = blockIdx.x;
    const int tid  = threadIdx.x;
    const int n8   = tid >> 3;     // node (0..31)
    const int q8   = tid & 7;      // slice
    const int warp = tid >> 5;
    const int lane = tid & 31;

    const float SQRT3    = 1.7320508075688772f;
    const float INVS3    = 0.5773502691896258f;
    const float C_S      = 0.14433756729740643f;  // 1/sqrt(48)
    const float INV_SQ32 = 0.17677669529663687f;
    const float R2       = 25.0f;

    // ---- stage Ws2n via cp.async; load statics ----
    cpa16((float4*)sW + tid, (const float4*)Ws2n + tid);
    cpa_commit();
    if (tid < 96) {
        int n = tid / 3, c = tid - n * 3;
        sm[SPOS + n * 4 + c] = pos[g * 96 + tid];
    }
    if (tid < 32) {
        sm[SPOS + tid * 4 + 3] = 0.f;
        sZi[tid] = z[g * 32 + tid];
    }
    __syncthreads();

    // ---- adjacency from pos (bit-identical to reference predicate) ----
    {
        const float4* pos4 = (const float4*)(sm + SPOS);
        float4 pm = pos4[lane];
        #pragma unroll
        for (int k = 0; k < 4; ++k) {
            int n = warp * 4 + k;
            float4 pn = pos4[n];
            float dx = __fsub_rn(pn.x, pm.x);
            float dy = __fsub_rn(pn.y, pm.y);
            float dz = __fsub_rn(pn.z, pm.z);
            float d2 = __fadd_rn(__fadd_rn(__fmul_rn(dx, dx), __fmul_rn(dy, dy)),
                                 __fmul_rn(dz, dz));
            unsigned msk = __ballot_sync(0xffffffffu, d2 <= R2 && d2 > 0.f);
            if (lane == 0) sAdj[n] = msk;
        }
    }

    // ---- emb gather, v = 0 ----
    {
        const float4* emb4 = (const float4*)emb;
        ((float4*)(sm + SSB + n8 * 36))[q8] = emb4[sZi[n8] * 8 + q8];
        float4 z4 = {0.f, 0.f, 0.f, 0.f};
        for (int i = tid; i < 544; i += 256) ((float4*)(sm + SV4))[i] = z4;
    }
    cpa_wait<0>();
    __syncthreads();

    // ---- initial s = (emb @ Ws2n)/sqrt(32), packed ----
    {
        u64 a01 = 0, a23 = 0;
        const float4* inf = (const float4*)(sm + SSB + n8 * 36);
        const ulonglong2* wf = (const ulonglong2*)sW;
        #pragma unroll
        for (int u4 = 0; u4 < 8; ++u4) {
            float4 s4 = inf[u4];
            float sv[4] = {s4.x, s4.y, s4.z, s4.w};
            #pragma unroll
            for (int j = 0; j < 4; ++j) {
                u64 sj = splat2(sv[j]);
                ulonglong2 w = wf[(u4 * 4 + j) * 8 + q8];
                ffma2(a01, sj, w.x);
                ffma2(a23, sj, w.y);
            }
        }
        float a0, a1, a2, a3;
        upk2(a01, a0, a1); upk2(a23, a2, a3);
        float4 o;
        o.x = a0 * INV_SQ32; o.y = a1 * INV_SQ32;
        o.z = a2 * INV_SQ32; o.w = a3 * INV_SQ32;
        ((float4*)(sm + SS + n8 * 36))[q8] = o;
    }
    __syncthreads();

    // ---- layers ----
    for (int l = 0; l < 3; ++l) {
        // stage weights: W1/W4/Ws raw, W2'/W3'/Wv' from g_wp (overlaps gather)
        {
            float4* wd = (float4*)sW;
            const float4* wp4 = (const float4*)(g_wp + l * 1024);
            cpa16(wd + tid,        (const float4*)W1g + l * 256 + tid);        // W1
            cpa16(wd + 576 + tid,  (const float4*)Wsg + l * 256 + tid);        // Ws
            if (tid < 128)
                cpa16(wd + 256 + tid, wp4 + tid);                              // W2'
            else
                cpa16(wd + 448 + (tid - 128),
                      (const float4*)W4g + l * 128 + (tid - 128));             // W4
            if (tid < 64)
                cpa16(wd + 384 + tid, wp4 + 128 + tid);                        // W3'
            else if (tid < 128)
                cpa16(wd + 832 + (tid - 64), wp4 + 192 + (tid - 64));          // Wv'
            cpa_commit();
        }

        // ---- edge gather: warp per 4 nodes, packed (x,y) pairs (v8) ----
        {
            int w2 = lane & 15;
            const float4* v4p = (const float4*)(sm + SV4);
            const float4* pos4 = (const float4*)(sm + SPOS);
            for (int k = 0; k < 4; ++k) {
                int n = warp * 4 + k;
                float4 pn = pos4[n];
                unsigned am = sAdj[n];
                float aS = 0.f, aPz = 0.f, aVz = 0.f, aRz = 0.f;
                u64 aPxy = 0, aVxy = 0, aRxy = 0;
                while (am) {
                    int m = __ffs(am) - 1;
                    am &= am - 1;
                    float4 pm = pos4[m];
                    float dx = pn.x - pm.x;
                    float dy = pn.y - pm.y;
                    float dz = pn.z - pm.z;
                    float iv = SQRT3 * rsqrtf(dx * dx + dy * dy + dz * dz);
                    float sx = dx * iv, sy = dy * iv, sz = dz * iv;
                    u64 sxy = pk2(sx, sy);
                    float su = sm[SS + m * 36 + lane];
                    aS += su;
                    ffma2(aPxy, splat2(su), sxy);
                    aPz = fmaf(su, sz, aPz);
                    ulonglong2 vv = *(const ulonglong2*)(v4p + m * 17 + w2);
                    fadd2(aVxy, vv.x);
                    float vz, vpad;
                    upk2(vv.y, vz, vpad);
                    aVz += vz;
                    ffma2(aRxy, vv.x, sxy);
                    aRz = fmaf(vz, sz, aRz);
                }
                float px, py, vxs, vys, rx, ry;
                upk2(aPxy, px, py);
                upk2(aVxy, vxs, vys);
                upk2(aRxy, rx, ry);
                sm[SSB + n * 36 + lane] = aS;
                sm[SP + (n * 3 + 0) * 36 + lane] = px;
                sm[SP + (n * 3 + 1) * 36 + lane] = py;
                sm[SP + (n * 3 + 2) * 36 + lane] = aPz;
                if (lane < 16) {
                    sm[SVB + (n * 3 + 0) * 20 + lane] = vxs;
                    sm[SVB + (n * 3 + 1) * 20 + lane] = vys;
                    sm[SVB + (n * 3 + 2) * 20 + lane] = aVz;
                    sm[SR + n * 20 + lane] = (rx + ry) + aRz;
                }
            }
        }
        cpa_wait<0>();
        __syncthreads();

        // ---- step A part 1: a_v_i = p_i@W2' + Vbar_i@W3' (C_VI folded) ----
        float avv[3][2];
        {
            const ulonglong2* w2p = (const ulonglong2*)(sW + 1024);
            const ulonglong2* w3p = (const ulonglong2*)(sW + 1536);
            #pragma unroll
            for (int i = 0; i < 3; ++i) {
                u64 b0 = 0, b1 = 0;
                mv32x16p((const u64*)(sm + SP + (n8 * 3 + i) * 36), w2p, q8, b0, b1);
                mv16x16p((const u64*)(sm + SVB + (n8 * 3 + i) * 20), w3p, q8, b0, b1);
                avv[i][0] = fold2(b0);
                avv[i][1] = fold2(b1);
            }
        }
        __syncthreads();   // all sP/sVb reads done; aliased region writable

        // step A part 2: write a_v; a_s = C_S*(Sbar@W1 + INVS3*r@W4) -> SAS
        {
            #pragma unroll
            for (int i = 0; i < 3; ++i)
                *(float2*)(sm + SAV + (n8 * 3 + i) * 20 + q8 * 2) =
                    make_float2(avv[i][0], avv[i][1]);

            u64 a01 = 0, a23 = 0;
            {
                const float4* inf = (const float4*)(sm + SSB + n8 * 36);
                const ulonglong2* wf = (const ulonglong2*)sW;
                #pragma unroll
                for (int u4 = 0; u4 < 8; ++u4) {
                    float4 s4 = inf[u4];
                    float sv[4] = {s4.x, s4.y, s4.z, s4.w};
                    #pragma unroll
                    for (int j = 0; j < 4; ++j) {
                        u64 sj = splat2(sv[j]);
                        ulonglong2 w = wf[(u4 * 4 + j) * 8 + q8];
                        ffma2(a01, sj, w.x);
                        ffma2(a23, sj, w.y);
                    }
                }
            }
            {
                const float4* inf = (const float4*)(sm + SR + n8 * 20);
                const ulonglong2* wf = (const ulonglong2*)(sW + 1792);
                #pragma unroll
                for (int u4 = 0; u4 < 4; ++u4) {
                    float4 r4 = inf[u4];
                    float rv[4] = {r4.x, r4.y, r4.z, r4.w};
                    #pragma unroll
                    for (int j = 0; j < 4; ++j) {
                        u64 rj = splat2(rv[j] * INVS3);
                        ulonglong2 w = wf[(u4 * 4 + j) * 8 + q8];
                        ffma2(a01, rj, w.x);
                        ffma2(a23, rj, w.y);
                    }
                }
            }
            float a0, a1, a2, a3;
            upk2(a01, a0, a1); upk2(a23, a2, a3);
            float4 o;
            o.x = C_S * a0; o.y = C_S * a1;
            o.z = C_S * a2; o.w = C_S * a3;
            ((float4*)(sm + SAS + n8 * 36))[q8] = o;
        }
        __syncthreads();

        // ---- step B: s += relu((a_s@Ws)/sqrt32); v_i += relu(a_v_i@Wv') ----
        {
            u64 a01 = 0, a23 = 0;
            const float4* inf = (const float4*)(sm + SAS + n8 * 36);
            const ulonglong2* wf = (const ulonglong2*)(sW + 2304);
            #pragma unroll
            for (int u4 = 0; u4 < 8; ++u4) {
                float4 a4 = inf[u4];
                float av_[4] = {a4.x, a4.y, a4.z, a4.w};
                #pragma unroll
                for (int j = 0; j < 4; ++j) {
                    u64 aj = splat2(av_[j]);
                    ulonglong2 w = wf[(u4 * 4 + j) * 8 + q8];
                    ffma2(a01, aj, w.x);
                    ffma2(a23, aj, w.y);
                }
            }
            float a0, a1, a2, a3;
            upk2(a01, a0, a1); upk2(a23, a2, a3);
            float4* sp = (float4*)(sm + SS + n8 * 36) + q8;
            float4 sv = *sp;
            sv.x += fmaxf(a0 * INV_SQ32, 0.f);
            sv.y += fmaxf(a1 * INV_SQ32, 0.f);
            sv.z += fmaxf(a2 * INV_SQ32, 0.f);
            sv.w += fmaxf(a3 * INV_SQ32, 0.f);
            *sp = sv;

            float hv[3][2];
            const ulonglong2* wvp = (const ulonglong2*)(sW + 3328);
            #pragma unroll
            for (int i = 0; i < 3; ++i) {
                u64 b0 = 0, b1 = 0;
                mv16x16p((const u64*)(sm + SAV + (n8 * 3 + i) * 20), wvp, q8, b0, b1);
                hv[i][0] = fold2(b0);
                hv[i][1] = fold2(b1);
            }
            float4* v4p = (float4*)(sm + SV4);
            #pragma unroll
            for (int k = 0; k < 2; ++k) {
                float4 vv = v4p[n8 * 17 + q8 * 2 + k];
                vv.x += fmaxf(hv[0][k], 0.f);
                vv.y += fmaxf(hv[1][k], 0.f);
                vv.z += fmaxf(hv[2][k], 0.f);
                v4p[n8 * 17 + q8 * 2 + k] = vv;
            }
        }
        __syncthreads();
    }

    // ---- pool ----
    if (tid < 80) {
        float acc = 0.f;
        if (tid < 32) {
            #pragma unroll
            for (int n = 0; n < 32; ++n) acc += sm[SS + n * 36 + tid];
        } else {
            int j = tid - 32;
            int w = j / 3, c = j - w * 3;
            #pragma unroll
            for (int n = 0; n < 32; ++n) acc += sm[SV4 + (n * 17 + w) * 4 + c];
        }
        g_hg[g * 80 + tid] = acc;
    }
}

// ---------------------------------------------------------------------------
// readout MLP (unchanged from v8): 16 graphs/CTA, single wave, cp.async
// double commit groups, H aliases the dead W1 buffer, packed f32x2 math.
// ---------------------------------------------------------------------------
#define MW1  0        // 20480 (W1; H [16][256] aliases after phase 1)
#define MH   0
#define MW2  20480    // 32768
#define MA   53248    // 1280 [g][80]
#define MB1  54528    // 256
#define MB2  54784    // 128
#define SMEM_MLP (54912 * 4)

__global__ void __launch_bounds__(256, 1) k_mlp(
    const float* __restrict__ Wr1, const float* __restrict__ br1,
    const float* __restrict__ Wr2, const float* __restrict__ br2,
    float* __restrict__ out, int B)
{
    extern __shared__ float sm[];
    const int tid = threadIdx.x;
    const int g0  = blockIdx.x * 16;

    // group 1: W1 + A + biases
    {
        float4* w1d = (float4*)(sm + MW1);
        const float4* w1s = (const float4*)Wr1;
        #pragma unroll
        for (int i = 0; i < 20; ++i)
            cpa16(w1d + tid + 256 * i, w1s + tid + 256 * i);
        for (int idx = tid; idx < 320; idx += 256) {
            int gg = idx / 20, c = idx % 20;
            if (g0 + gg < B)
                cpa16((float4*)(sm + MA + gg * 80) + c,
                      (const float4*)(g_hg + (size_t)(g0 + gg) * 80) + c);
        }
        if (tid < 64)  cpa16((float4*)(sm + MB1) + tid, (const float4*)br1 + tid);
        if (tid < 32)  cpa16((float4*)(sm + MB2) + tid, (const float4*)br2 + tid);
        cpa_commit();
    }
    // group 2: W2
    {
        float4* w2d = (float4*)(sm + MW2);
        const float4* w2s = (const float4*)Wr2;
        #pragma unroll
        for (int i = 0; i < 32; ++i)
            cpa16(w2d + tid + 256 * i, w2s + tid + 256 * i);
        cpa_commit();
    }

    cpa_wait<1>();           // W1 + A ready (W2 still in flight)
    __syncthreads();

    // phase 1 -> registers: 4 graphs x 4 outputs per thread, packed
    const int gq = tid >> 6;
    const int oq = tid & 63;
    u64 c01[4], c23[4];
    #pragma unroll
    for (int gi = 0; gi < 4; ++gi) { c01[gi] = 0; c23[gi] = 0; }
    {
        const ulonglong2* w4p = (const ulonglong2*)(sm + MW1);
        #pragma unroll 4
        for (int k = 0; k < 80; ++k) {
            ulonglong2 w = w4p[k * 64 + oq];
            #pragma unroll
            for (int gi = 0; gi < 4; ++gi) {
                u64 a2 = splat2(sm[MA + (4 * gq + gi) * 80 + k]);
                ffma2(c01[gi], a2, w.x);
                ffma2(c23[gi], a2, w.y);
            }
        }
    }
    float4 b4 = ((const float4*)(sm + MB1))[oq];
    __syncthreads();         // all W1 reads done before H overwrites it

    {
        float4* h4p = (float4*)(sm + MH);
        #pragma unroll
        for (int gi = 0; gi < 4; ++gi) {
            float x0, x1, x2, x3;
            upk2(c01[gi], x0, x1); upk2(c23[gi], x2, x3);
            float4 hv;
            hv.x = fmaxf(x0 + b4.x, 0.f);
            hv.y = fmaxf(x1 + b4.y, 0.f);
            hv.z = fmaxf(x2 + b4.z, 0.f);
            hv.w = fmaxf(x3 + b4.w, 0.f);
            h4p[(4 * gq + gi) * 64 + oq] = hv;
        }
    }
    cpa_wait<0>();           // W2 ready
    __syncthreads();

    // phase 2: 2 graphs x 4 outputs per thread, packed
    {
        const int g2 = tid >> 5;
        const int o2 = tid & 31;
        u64 d0a = 0, d0b = 0, d1a = 0, d1b = 0;
        const ulonglong2* w4p = (const ulonglong2*)(sm + MW2);
        const float* h0 = sm + MH + (2 * g2) * 256;
        const float* h1 = sm + MH + (2 * g2 + 1) * 256;
        #pragma unroll 4
        for (int k = 0; k < 256; ++k) {
            u64 a0 = splat2(h0[k]);
            u64 a1 = splat2(h1[k]);
            ulonglong2 w = w4p[k * 32 + o2];
            ffma2(d0a, a0, w.x); ffma2(d0b, a0, w.y);
            ffma2(d1a, a1, w.x); ffma2(d1b, a1, w.y);
        }
        float4 bb = ((const float4*)(sm + MB2))[o2];
        int ga = g0 + 2 * g2, gb = ga + 1;
        float e0, e1, e2, e3;
        if (ga < B) {
            upk2(d0a, e0, e1); upk2(d0b, e2, e3);
            float4 o; o.x = e0 + bb.x; o.y = e1 + bb.y;
            o.z = e2 + bb.z; o.w = e3 + bb.w;
            ((float4*)(out + (size_t)ga * 128))[o2] = o;
        }
        if (gb < B) {
            upk2(d1a, e0, e1); upk2(d1b, e2, e3);
            float4 o; o.x = e0 + bb.x; o.y = e1 + bb.y;
            o.z = e2 + bb.z; o.w = e3 + bb.w;
            ((float4*)(out + (size_t)gb * 128))[o2] = o;
        }
    }
}

extern "C" void kernel_launch(void* const* d_in, const int* in_sizes, int n_in,
                              void* d_out, int out_size)
{
    int ie = -1;
    for (int i = 0; i < n_in; ++i)
        if (in_sizes[i] == 3200) { ie = i; break; }
    if (ie < 0) return;

    const float* pos = (const float*)d_in[0];
    int N = in_sizes[0] / 3;
    int B = N / 32;

    const float* emb  = (const float*)d_in[ie];
    const float* Ws2n = (const float*)d_in[ie + 1];
    const float* W1   = (const float*)d_in[ie + 2];
    const float* W2   = (const float*)d_in[ie + 3];
    const float* W3   = (const float*)d_in[ie + 4];
    const float* W4   = (const float*)d_in[ie + 5];
    const float* Ws   = (const float*)d_in[ie + 6];
    const float* Wv   = (const float*)d_in[ie + 7];
    const float* Wr1  = (const float*)d_in[ie + 8];
    const float* br1  = (const float*)d_in[ie + 9];
    const float* Wr2  = (const float*)d_in[ie + 10];
    const float* br2  = (const float*)d_in[ie + 11];

    const int* z = nullptr;
    for (int i = 1; i < n_in; ++i) {
        if (i >= ie && i <= ie + 11) continue;
        if (in_sizes[i] == N) { z = (const int*)d_in[i]; break; }  // z precedes batch
    }
    if (!z || B > MAXB || N > MAXN) return;

    cudaFuncSetAttribute((const void*)k_gnn,
                         cudaFuncAttributeMaxDynamicSharedMemorySize, SMEM_GNN);
    cudaFuncSetAttribute((const void*)k_mlp,
                         cudaFuncAttributeMaxDynamicSharedMemorySize, SMEM_MLP);

    k_pack<<<(WPAKN + 255) / 256, 256>>>(W2, W3, Wv);
    k_gnn<<<B, 256, SMEM_GNN>>>(pos, z, emb, Ws2n, W1, W4, Ws);
    k_mlp<<<(B + 15) / 16, 256, SMEM_MLP>>>(Wr1, br1, Wr2, br2, (float*)d_out, B);
}